// round 15
// baseline (speedup 1.0000x reference)
#include <cuda_runtime.h>

// 2-layer LSTM (HID=10) + linear head, B=2048, T=1024, future=64.
// Round 15: R13 math/mapping (3 batches/warp, 10-lane groups, split
// accumulators, carried vd) restructured for scheduler freedom:
//  - shared loads: volatile asm WITHOUT memory clobber (no barriers)
//  - stores: volatile asm WITH clobber (3 barriers/step instead of 13)
//  - loop re-staged: act1(t+1) inside iter t; whh2.vd + head issued
//    under act1's MUFU chain; vd reloaded at iter end, consumed after
//    the next iter's 40-FFMA2 shared loop (latency fully covered).
//  - uniform grid 86 x 256: 2 warps/SMSP everywhere, single wave.

#define HID 10
#define T_FIXED 1024

typedef unsigned long long u64;

__device__ __forceinline__ u64 pack2(float lo, float hi) {
    u64 d; asm("mov.b64 %0, {%1, %2};" : "=l"(d) : "f"(lo), "f"(hi)); return d;
}
__device__ __forceinline__ void unpack2(u64 d, float& lo, float& hi) {
    asm("mov.b64 {%0, %1}, %2;" : "=f"(lo), "=f"(hi) : "l"(d));
}
__device__ __forceinline__ u64 ffma2(u64 a, u64 b, u64 c) {
    u64 d; asm("fma.rn.f32x2 %0, %1, %2, %3;" : "=l"(d) : "l"(a), "l"(b), "l"(c));
    return d;
}
__device__ __forceinline__ float psum(u64 a) {
    float l, h; unpack2(a, l, h); return l + h;
}
__device__ __forceinline__ float tanh_hw(float v) {
    float r; asm("tanh.approx.f32 %0, %1;" : "=f"(r) : "f"(v)); return r;
}

// Gates gi,gf,go arrive PRE-HALVED (weights/biases scaled by 0.5).
__device__ __forceinline__ float cell_update_h(
    float gi_h, float gf_h, float gg, float go_h, float& c)
{
    float si = fmaf(tanh_hw(gi_h), 0.5f, 0.5f);
    float sf = fmaf(tanh_hw(gf_h), 0.5f, 0.5f);
    float so = fmaf(tanh_hw(go_h), 0.5f, 0.5f);
    float tg = tanh_hw(gg);
    c = fmaf(sf, c, si * tg);
    return so * tanh_hw(c);
}

// ---- shared memory access: loads free to schedule, stores are barriers ----
__device__ __forceinline__ float lds32(const float* p) {
    float v; unsigned a = (unsigned)__cvta_generic_to_shared(p);
    asm volatile("ld.shared.b32 %0, [%1];" : "=f"(v) : "r"(a));
    return v;
}
__device__ __forceinline__ void load_vec10(const float* p, u64* v) {
    unsigned a = (unsigned)__cvta_generic_to_shared(p);
    asm volatile("ld.shared.v2.b64 {%0,%1}, [%2];"
                 : "=l"(v[0]), "=l"(v[1]) : "r"(a));
    asm volatile("ld.shared.v2.b64 {%0,%1}, [%2];"
                 : "=l"(v[2]), "=l"(v[3]) : "r"(a + 16));
    asm volatile("ld.shared.b64 %0, [%1];"
                 : "=l"(v[4]) : "r"(a + 32));
}
__device__ __forceinline__ void sts32(float* p, float v) {
    unsigned a = (unsigned)__cvta_generic_to_shared(p);
    asm volatile("st.shared.b32 [%0], %1;" :: "r"(a), "f"(v) : "memory");
}

// Per-warp smem layout (floats): h1[3][12] | h2[3][12] | x[3][20] | y[3][20]
#define SW_H1 0
#define SW_H2 36
#define SW_X  72
#define SW_Y  132
#define SW_WARP 192
#define WPB 8

__global__ void __launch_bounds__(32 * WPB, 1)
lstm2_seq_kernel(
    const float* __restrict__ x,
    const float* __restrict__ W_ih1, const float* __restrict__ W_hh1,
    const float* __restrict__ b_ih1, const float* __restrict__ b_hh1,
    const float* __restrict__ W_ih2, const float* __restrict__ W_hh2,
    const float* __restrict__ b_ih2, const float* __restrict__ b_hh2,
    const float* __restrict__ W_lin, const float* __restrict__ b_lin,
    float* __restrict__ out,
    int B, int T, int outT)
{
    __shared__ __align__(16) float sm[WPB * SW_WARP];

    const int lane   = threadIdx.x & 31;
    const int warpIn = threadIdx.x >> 5;
    const int warpGl = blockIdx.x * WPB + warpIn;
    const int g      = lane / 10;          // 0..2 active groups; 3 = idle
    const int k      = lane - g * 10;      // unit index within group
    const int gc     = (g < 3) ? g : 0;
    const int warpB0 = warpGl * 3;
    const int b      = warpB0 + gc;
    const bool alane = (g < 3) && (b < B);
    float* sw = sm + warpIn * SW_WARP;

    // ---- per-lane weights; i/f/o rows (q != 2) pre-scaled by 0.5 ----
    float wih1[4], b1[4], b2[4];
    u64 whh1[4][5], wih2[4][5], whh2[4][5], wlinp[5];
#pragma unroll
    for (int q = 0; q < 4; q++) {
        const float sc = (q == 2) ? 1.0f : 0.5f;
        const int r = q * HID + k;
        wih1[q] = (alane ? W_ih1[r] : 0.0f) * sc;
        b1[q]   = (alane ? (b_ih1[r] + b_hh1[r]) : 0.0f) * sc;
        b2[q]   = (alane ? (b_ih2[r] + b_hh2[r]) : 0.0f) * sc;
#pragma unroll
        for (int p = 0; p < 5; p++) {
            whh1[q][p] = pack2((alane ? W_hh1[r*HID+2*p]   : 0.0f) * sc,
                               (alane ? W_hh1[r*HID+2*p+1] : 0.0f) * sc);
            wih2[q][p] = pack2((alane ? W_ih2[r*HID+2*p]   : 0.0f) * sc,
                               (alane ? W_ih2[r*HID+2*p+1] : 0.0f) * sc);
            whh2[q][p] = pack2((alane ? W_hh2[r*HID+2*p]   : 0.0f) * sc,
                               (alane ? W_hh2[r*HID+2*p+1] : 0.0f) * sc);
        }
    }
#pragma unroll
    for (int p = 0; p < 5; p++) wlinp[p] = pack2(W_lin[2*p], W_lin[2*p+1]);
    const float blin = b_lin[0];

    // zero h vectors; barrier so later un-clobbered loads can't float above
    for (int i = lane; i < 72; i += 32) sw[i] = 0.0f;
    asm volatile("" ::: "memory");

    float c1 = 0.0f, c2 = 0.0f;

    // ---- x / y staging helpers ----
    float xr0 = 0.0f, xr1 = 0.0f;
    auto ldg_chunk = [&](int t0, float& r0, float& r1) {
        int g0_ = lane >> 4, c0_ = lane & 15;
        int bb0 = warpB0 + g0_;
        r0 = (bb0 < B) ? x[(size_t)bb0 * T + t0 + c0_] : 0.0f;
        int bb1 = warpB0 + 2;
        r1 = (lane < 16 && bb1 < B) ? x[(size_t)bb1 * T + t0 + lane] : 0.0f;
    };
    auto sts_chunk = [&](float r0, float r1) {
        sts32(sw + SW_X + (lane >> 4) * 20 + (lane & 15), r0);
        if (lane < 16) sts32(sw + SW_X + 2 * 20 + lane, r1);
    };
    auto flush_y = [&](int t0) {
#pragma unroll
        for (int r2 = 0; r2 < 2; r2++) {
            int idx = lane + r2 * 32;
            if (idx < 48) {
                int gg = idx >> 4, ii = idx & 15;
                int bb = warpB0 + gg;
                if (bb < B)
                    out[(size_t)bb * outT + t0 + ii] = lds32(sw + SW_Y + gg*20 + ii);
            }
        }
    };

    // prologue: commit chunk 0, prefetch chunk 16
    { float a0, a1; ldg_chunk(0, a0, a1); sts_chunk(a0, a1); }
    if (T > 16) ldg_chunk(16, xr0, xr1);

    // h1(0) = act1(b1 + wih1*x0), since h1(-1)=0; store it.
    {
        float x0 = lds32(sw + SW_X + gc * 20);
        float h1 = cell_update_h(fmaf(wih1[0], x0, b1[0]),
                                 fmaf(wih1[1], x0, b1[1]),
                                 fmaf(wih1[2], x0, b1[2]),
                                 fmaf(wih1[3], x0, b1[3]), c1);
        if (alane) sts32(sw + SW_H1 + gc * 12 + k, h1);
    }

    // carried vd = h2(-1) = zeros
    u64 vd[5];
    load_vec10(sw + SW_H2 + gc * 12, vd);

    // ---- main loop: iter t advances layer1 to t+1, layer2 to t ----
#pragma unroll 1
    for (int t = 0; t < T - 1; t++) {
        // x chunk boundary: commit prefetched chunk holding x(t+1)
        int tn = t + 1;
        if ((tn & 15) == 0) {
            sts_chunk(xr0, xr1);
            int t0n = tn + 16;
            if (t0n < T) ldg_chunk(t0n, xr0, xr1);
        }
        float xt1 = lds32(sw + SW_X + gc * 20 + (tn & 15));

        // N = layer-1 gates for step t+1 (init with x term)
        u64 N0 = pack2(fmaf(wih1[0], xt1, b1[0]), 0.0f);
        u64 N1 = pack2(fmaf(wih1[1], xt1, b1[1]), 0.0f);
        u64 N2 = pack2(fmaf(wih1[2], xt1, b1[2]), 0.0f);
        u64 N3 = pack2(fmaf(wih1[3], xt1, b1[3]), 0.0f);
        // A partial: layer-2 input part (wih2 . h1(t)) with bias
        u64 A0 = pack2(b2[0], 0.0f), A1 = pack2(b2[1], 0.0f);
        u64 A2 = pack2(b2[2], 0.0f), A3 = pack2(b2[3], 0.0f);

        // shared h1(t) broadcast loop (vd not needed yet — its LDS from the
        // previous iteration completes under this loop's 40 FFMA2)
        u64 w[5];
        load_vec10(sw + SW_H1 + gc * 12, w);
#pragma unroll
        for (int p = 0; p < 5; p++) {
            A0 = ffma2(wih2[0][p], w[p], A0);
            A1 = ffma2(wih2[1][p], w[p], A1);
            A2 = ffma2(wih2[2][p], w[p], A2);
            A3 = ffma2(wih2[3][p], w[p], A3);
            N0 = ffma2(whh1[0][p], w[p], N0);
            N1 = ffma2(whh1[1][p], w[p], N1);
            N2 = ffma2(whh1[2][p], w[p], N2);
            N3 = ffma2(whh1[3][p], w[p], N3);
        }

        // act1 for step t+1; store h1(t+1)
        float h1 = cell_update_h(psum(N0), psum(N1), psum(N2), psum(N3), c1);
        if (alane) sts32(sw + SW_H1 + gc * 12 + k, h1);

        // under act1's MUFU chain: finish A with whh2 . h2(t-1) and head
        u64 Y = pack2(blin, 0.0f);
#pragma unroll
        for (int p = 0; p < 5; p++) {
            A0 = ffma2(whh2[0][p], vd[p], A0);
            A1 = ffma2(whh2[1][p], vd[p], A1);
            A2 = ffma2(whh2[2][p], vd[p], A2);
            A3 = ffma2(whh2[3][p], vd[p], A3);
            Y  = ffma2(wlinp[p],   vd[p], Y);
        }
        if (alane && k == 0) sts32(sw + SW_Y + gc * 20 + ((t - 1) & 15), psum(Y));

        // act2 for step t; store h2(t); reload vd for next iteration
        float h2 = cell_update_h(psum(A0), psum(A1), psum(A2), psum(A3), c2);
        if (alane) sts32(sw + SW_H2 + gc * 12 + k, h2);
        load_vec10(sw + SW_H2 + gc * 12, vd);

        if ((t & 15) == 0 && t > 0) flush_y(t - 16);
    }

    // ---- tail: layer2 for step T-1 (h1(T-1) already computed) ----
    {
        u64 w[5];
        load_vec10(sw + SW_H1 + gc * 12, w);       // h1(T-1)
        u64 A0 = pack2(b2[0], 0.0f), A1 = pack2(b2[1], 0.0f);
        u64 A2 = pack2(b2[2], 0.0f), A3 = pack2(b2[3], 0.0f);
        u64 Y = pack2(blin, 0.0f);
#pragma unroll
        for (int p = 0; p < 5; p++) {
            A0 = ffma2(wih2[0][p], w[p], A0);  A0 = ffma2(whh2[0][p], vd[p], A0);
            A1 = ffma2(wih2[1][p], w[p], A1);  A1 = ffma2(whh2[1][p], vd[p], A1);
            A2 = ffma2(wih2[2][p], w[p], A2);  A2 = ffma2(whh2[2][p], vd[p], A2);
            A3 = ffma2(wih2[3][p], w[p], A3);  A3 = ffma2(whh2[3][p], vd[p], A3);
            Y  = ffma2(wlinp[p],  vd[p], Y);
        }
        if (alane && k == 0) sts32(sw + SW_Y + gc * 20 + ((T - 2) & 15), psum(Y));
        float h2 = cell_update_h(psum(A0), psum(A1), psum(A2), psum(A3), c2);
        if (alane) sts32(sw + SW_H2 + gc * 12 + k, h2);
        load_vec10(sw + SW_H2 + gc * 12, vd);
    }
    // y(T-1) from fresh h2(T-1)
    float yfb;
    {
        u64 Y = pack2(blin, 0.0f);
#pragma unroll
        for (int p = 0; p < 5; p++) Y = ffma2(wlinp[p], vd[p], Y);
        yfb = psum(Y);
        if (alane && k == 0) sts32(sw + SW_Y + gc * 20 + ((T - 1) & 15), yfb);
    }
    flush_y(T - 16);

    // ---- future steps: full step with y feedback ----
#pragma unroll 1
    for (int t = T; t < outT; t++) {
        u64 w[5];
        // layer 1
        load_vec10(sw + SW_H1 + gc * 12, w);       // h1(t-1)
        u64 N0 = pack2(fmaf(wih1[0], yfb, b1[0]), 0.0f);
        u64 N1 = pack2(fmaf(wih1[1], yfb, b1[1]), 0.0f);
        u64 N2 = pack2(fmaf(wih1[2], yfb, b1[2]), 0.0f);
        u64 N3 = pack2(fmaf(wih1[3], yfb, b1[3]), 0.0f);
#pragma unroll
        for (int p = 0; p < 5; p++) {
            N0 = ffma2(whh1[0][p], w[p], N0);
            N1 = ffma2(whh1[1][p], w[p], N1);
            N2 = ffma2(whh1[2][p], w[p], N2);
            N3 = ffma2(whh1[3][p], w[p], N3);
        }
        float h1 = cell_update_h(psum(N0), psum(N1), psum(N2), psum(N3), c1);
        if (alane) sts32(sw + SW_H1 + gc * 12 + k, h1);

        // layer 2 (vd = h2(t-1))
        load_vec10(sw + SW_H1 + gc * 12, w);       // h1(t)
        u64 A0 = pack2(b2[0], 0.0f), A1 = pack2(b2[1], 0.0f);
        u64 A2 = pack2(b2[2], 0.0f), A3 = pack2(b2[3], 0.0f);
#pragma unroll
        for (int p = 0; p < 5; p++) {
            A0 = ffma2(wih2[0][p], w[p], A0);  A0 = ffma2(whh2[0][p], vd[p], A0);
            A1 = ffma2(wih2[1][p], w[p], A1);  A1 = ffma2(whh2[1][p], vd[p], A1);
            A2 = ffma2(wih2[2][p], w[p], A2);  A2 = ffma2(whh2[2][p], vd[p], A2);
            A3 = ffma2(wih2[3][p], w[p], A3);  A3 = ffma2(whh2[3][p], vd[p], A3);
        }
        float h2 = cell_update_h(psum(A0), psum(A1), psum(A2), psum(A3), c2);
        if (alane) sts32(sw + SW_H2 + gc * 12 + k, h2);
        load_vec10(sw + SW_H2 + gc * 12, vd);

        // head from fresh h2(t)
        u64 Y = pack2(blin, 0.0f);
#pragma unroll
        for (int p = 0; p < 5; p++) Y = ffma2(wlinp[p], vd[p], Y);
        yfb = psum(Y);
        if (alane && k == 0) sts32(sw + SW_Y + gc * 20 + (t & 15), yfb);

        if ((t & 15) == 15) flush_y(t & ~15);
    }
    if (outT & 15) flush_y(outT & ~15);
}

extern "C" void kernel_launch(void* const* d_in, const int* in_sizes, int n_in,
                              void* d_out, int out_size)
{
    const float* x     = (const float*)d_in[0];
    const float* W_ih1 = (const float*)d_in[1];
    const float* W_hh1 = (const float*)d_in[2];
    const float* b_ih1 = (const float*)d_in[3];
    const float* b_hh1 = (const float*)d_in[4];
    const float* W_ih2 = (const float*)d_in[5];
    const float* W_hh2 = (const float*)d_in[6];
    const float* b_ih2 = (const float*)d_in[7];
    const float* b_hh2 = (const float*)d_in[8];
    const float* W_lin = (const float*)d_in[9];
    const float* b_lin = (const float*)d_in[10];
    float* out = (float*)d_out;

    const int T = T_FIXED;
    const int B = in_sizes[0] / T;          // 2048
    const int outT = out_size / B;          // T + future = 1088

    // 3 batches/warp, 8 warps/block -> uniform 2 warps/SMSP, single wave.
    const int nWarps  = (B + 2) / 3;                    // 683
    const int nBlocks = (nWarps + WPB - 1) / WPB;       // 86
    lstm2_seq_kernel<<<nBlocks, 32 * WPB>>>(
        x, W_ih1, W_hh1, b_ih1, b_hh1,
        W_ih2, W_hh2, b_ih2, b_hh2,
        W_lin, b_lin, out, B, T, outT);
}

// round 16
// speedup vs baseline: 1.7203x; 1.7203x over previous
#include <cuda_runtime.h>

// 2-layer LSTM (HID=10) + linear head, B=2048, T=1024, future=64.
// Round 16: R13 (best, 308.8us) with ONLY the per-step head removed:
//  - h2 stored into a 16-slot rotating history (same STS cost)
//  - every 16 steps, a batched flush computes 48 y-values (16 steps x 3
//    batches) across all 32 lanes and stores them coalesced to gmem
//  - main-loop ordering, grid (171x128), math otherwise IDENTICAL to R13.

#define HID 10
#define T_FIXED 1024

typedef unsigned long long u64;

__device__ __forceinline__ u64 pack2(float lo, float hi) {
    u64 d; asm("mov.b64 %0, {%1, %2};" : "=l"(d) : "f"(lo), "f"(hi)); return d;
}
__device__ __forceinline__ void unpack2(u64 d, float& lo, float& hi) {
    asm("mov.b64 {%0, %1}, %2;" : "=f"(lo), "=f"(hi) : "l"(d));
}
__device__ __forceinline__ u64 ffma2(u64 a, u64 b, u64 c) {
    u64 d; asm("fma.rn.f32x2 %0, %1, %2, %3;" : "=l"(d) : "l"(a), "l"(b), "l"(c));
    return d;
}
__device__ __forceinline__ float psum(u64 a) {
    float l, h; unpack2(a, l, h); return l + h;
}
__device__ __forceinline__ float tanh_hw(float v) {
    float r; asm("tanh.approx.f32 %0, %1;" : "=f"(r) : "f"(v)); return r;
}

// Gates gi,gf,go arrive PRE-HALVED (weights/biases scaled by 0.5).
__device__ __forceinline__ float cell_update_h(
    float gi_h, float gf_h, float gg, float go_h, float& c)
{
    float si = fmaf(tanh_hw(gi_h), 0.5f, 0.5f);
    float sf = fmaf(tanh_hw(gf_h), 0.5f, 0.5f);
    float so = fmaf(tanh_hw(go_h), 0.5f, 0.5f);
    float tg = tanh_hw(gg);
    c = fmaf(sf, c, si * tg);
    return so * tanh_hw(c);
}

// Load 10 floats (5 packed f32x2) from 16B-aligned smem. (R13 semantics:
// volatile + memory clobber — proven ordering.)
__device__ __forceinline__ void load_vec10(const float* p, u64* v) {
    unsigned a = (unsigned)__cvta_generic_to_shared(p);
    asm volatile("ld.shared.v2.b64 {%0,%1}, [%2];"
                 : "=l"(v[0]), "=l"(v[1]) : "r"(a) : "memory");
    asm volatile("ld.shared.v2.b64 {%0,%1}, [%2];"
                 : "=l"(v[2]), "=l"(v[3]) : "r"(a + 16) : "memory");
    asm volatile("ld.shared.b64 %0, [%1];"
                 : "=l"(v[4]) : "r"(a + 32) : "memory");
}

// Per-warp smem layout (floats):
//   h1[3][12] | h2hist[16][3][12] | x[3][20]
#define SW_H1   0
#define SW_HIST 36
#define SW_X    612
#define SW_WARP 672        // 2688 B per warp, 16B-divisible

__global__ void __launch_bounds__(128, 1)
lstm2_seq_kernel(
    const float* __restrict__ x,
    const float* __restrict__ W_ih1, const float* __restrict__ W_hh1,
    const float* __restrict__ b_ih1, const float* __restrict__ b_hh1,
    const float* __restrict__ W_ih2, const float* __restrict__ W_hh2,
    const float* __restrict__ b_ih2, const float* __restrict__ b_hh2,
    const float* __restrict__ W_lin, const float* __restrict__ b_lin,
    float* __restrict__ out,
    int B, int T, int outT)
{
    __shared__ __align__(16) float sm[4 * SW_WARP];

    const int lane   = threadIdx.x & 31;
    const int warpIn = threadIdx.x >> 5;
    const int warpGl = blockIdx.x * 4 + warpIn;
    const int g      = lane / 10;          // 0..2 active groups; 3 = idle
    const int k      = lane - g * 10;      // unit index within group
    const int gc     = (g < 3) ? g : 0;
    const int warpB0 = warpGl * 3;
    const int b      = warpB0 + gc;
    const bool alane = (g < 3) && (b < B);
    float* sw = sm + warpIn * SW_WARP;

    // ---- per-lane weights; i/f/o rows (q != 2) pre-scaled by 0.5 ----
    float wih1[4], b1[4], b2[4];
    u64 whh1[4][5], wih2[4][5], whh2[4][5], wlinp[5];
#pragma unroll
    for (int q = 0; q < 4; q++) {
        const float sc = (q == 2) ? 1.0f : 0.5f;
        const int r = q * HID + k;
        wih1[q] = (alane ? W_ih1[r] : 0.0f) * sc;
        b1[q]   = (alane ? (b_ih1[r] + b_hh1[r]) : 0.0f) * sc;
        b2[q]   = (alane ? (b_ih2[r] + b_hh2[r]) : 0.0f) * sc;
#pragma unroll
        for (int p = 0; p < 5; p++) {
            whh1[q][p] = pack2((alane ? W_hh1[r*HID+2*p]   : 0.0f) * sc,
                               (alane ? W_hh1[r*HID+2*p+1] : 0.0f) * sc);
            wih2[q][p] = pack2((alane ? W_ih2[r*HID+2*p]   : 0.0f) * sc,
                               (alane ? W_ih2[r*HID+2*p+1] : 0.0f) * sc);
            whh2[q][p] = pack2((alane ? W_hh2[r*HID+2*p]   : 0.0f) * sc,
                               (alane ? W_hh2[r*HID+2*p+1] : 0.0f) * sc);
        }
    }
#pragma unroll
    for (int p = 0; p < 5; p++) wlinp[p] = pack2(W_lin[2*p], W_lin[2*p+1]);
    const float blin = b_lin[0];

    float c1 = 0.0f, c2 = 0.0f;

    // ---- x staging helpers (R13) ----
    float xr0 = 0.0f, xr1 = 0.0f;
    auto ldg_chunk = [&](int t0, float& r0, float& r1) {
        int g0_ = lane >> 4, c0_ = lane & 15;
        int bb0 = warpB0 + g0_;
        r0 = (bb0 < B) ? x[(size_t)bb0 * T + t0 + c0_] : 0.0f;
        int bb1 = warpB0 + 2;
        r1 = (lane < 16 && bb1 < B) ? x[(size_t)bb1 * T + t0 + lane] : 0.0f;
    };
    auto sts_chunk = [&](float r0, float r1) {
        sw[SW_X + (lane >> 4) * 20 + (lane & 15)] = r0;
        if (lane < 16) sw[SW_X + 2 * 20 + lane] = r1;
    };

    // Batched head: y(t0+s) for s in [0,16) x 3 batches, from h2 history.
    // 48 dots over 32 lanes (2 rounds); coalesced 16-wide STG per batch.
    auto flush_y = [&](int t0) {
#pragma unroll
        for (int r2 = 0; r2 < 2; r2++) {
            int idx = lane + r2 * 32;
            if (idx < 48) {
                int s  = idx & 15;
                int gb = idx >> 4;                 // 0..2
                u64 hv[5];
                load_vec10(sw + SW_HIST + s * 36 + gb * 12, hv);
                u64 Y = pack2(blin, 0.0f);
#pragma unroll
                for (int p = 0; p < 5; p++) Y = ffma2(wlinp[p], hv[p], Y);
                int bb = warpB0 + gb;
                if (bb < B && t0 + s < outT)
                    out[(size_t)bb * outT + t0 + s] = psum(Y);
            }
        }
    };

    // prologue: commit chunk 0, prefetch chunk 16
    { float a0, a1; ldg_chunk(0, a0, a1); sts_chunk(a0, a1); }
    if (T > 16) ldg_chunk(16, xr0, xr1);

    // carried vd = h2(-1) = zeros (registers; no smem zeroing needed)
    u64 vd[5];
#pragma unroll
    for (int p = 0; p < 5; p++) vd[p] = pack2(0.0f, 0.0f);

    // gates for step 0 (h1(-1) = 0)
    float x0 = sw[SW_X + gc * 20 + 0];
    u64 G0 = pack2(fmaf(wih1[0], x0, b1[0]), 0.0f);
    u64 G1 = pack2(fmaf(wih1[1], x0, b1[1]), 0.0f);
    u64 G2 = pack2(fmaf(wih1[2], x0, b1[2]), 0.0f);
    u64 G3 = pack2(fmaf(wih1[3], x0, b1[3]), 0.0f);

    // ---- pipelined main loop: steps 0 .. T-2 (R13 ordering) ----
#pragma unroll 1
    for (int t = 0; t < T - 1; t++) {
        // flush completed y block BEFORE this iter's h2 overwrites slot t&15
        if ((t & 15) == 0 && t > 0) flush_y(t - 16);

        // A = b2 + Whh2 . h2(t-1) from carried vd
        u64 A0 = pack2(b2[0], 0.0f), A1 = pack2(b2[1], 0.0f);
        u64 A2 = pack2(b2[2], 0.0f), A3 = pack2(b2[3], 0.0f);
#pragma unroll
        for (int p = 0; p < 5; p++) {
            A0 = ffma2(whh2[0][p], vd[p], A0);
            A1 = ffma2(whh2[1][p], vd[p], A1);
            A2 = ffma2(whh2[2][p], vd[p], A2);
            A3 = ffma2(whh2[3][p], vd[p], A3);
        }

        // layer-1 activation for step t (consumes G)
        float h1 = cell_update_h(psum(G0), psum(G1), psum(G2), psum(G3), c1);
        if (alane) sw[SW_H1 + gc * 12 + k] = h1;

        // x(t+1): commit prefetched chunk at boundaries, prefetch next
        int tn = t + 1;
        if ((tn & 15) == 0) {
            sts_chunk(xr0, xr1);
            int t0n = tn + 16;
            if (t0n < T) ldg_chunk(t0n, xr0, xr1);
        }
        float xt1 = sw[SW_X + gc * 20 + (tn & 15)];

        // gates for step t+1 (layer 1) init
        u64 N0 = pack2(fmaf(wih1[0], xt1, b1[0]), 0.0f);
        u64 N1 = pack2(fmaf(wih1[1], xt1, b1[1]), 0.0f);
        u64 N2 = pack2(fmaf(wih1[2], xt1, b1[2]), 0.0f);
        u64 N3 = pack2(fmaf(wih1[3], xt1, b1[3]), 0.0f);

        // shared h1(t) broadcast: feeds ih2 (step t) and hh1 (step t+1)
        u64 w[5];
        load_vec10(sw + SW_H1 + gc * 12, w);
#pragma unroll
        for (int p = 0; p < 5; p++) {
            A0 = ffma2(wih2[0][p], w[p], A0);
            A1 = ffma2(wih2[1][p], w[p], A1);
            A2 = ffma2(wih2[2][p], w[p], A2);
            A3 = ffma2(wih2[3][p], w[p], A3);
            N0 = ffma2(whh1[0][p], w[p], N0);
            N1 = ffma2(whh1[1][p], w[p], N1);
            N2 = ffma2(whh1[2][p], w[p], N2);
            N3 = ffma2(whh1[3][p], w[p], N3);
        }
        G0 = N0; G1 = N1; G2 = N2; G3 = N3;

        // layer-2 activation for step t; store into history slot; re-carry vd
        float h2 = cell_update_h(psum(A0), psum(A1), psum(A2), psum(A3), c2);
        float* hslot = sw + SW_HIST + (t & 15) * 36 + gc * 12;
        if (alane) hslot[k] = h2;
        load_vec10(hslot, vd);
    }

    // ---- tail: step T-1 with x[T-1], then future steps with y feedback ----
    float xt = sw[SW_X + gc * 20 + 15];   // x[T-1]
#pragma unroll 1
    for (int t = T - 1; t < outT; t++) {
        u64 w[5];

        // layer 1
        load_vec10(sw + SW_H1 + gc * 12, w);     // h1(t-1)
        u64 g0 = pack2(fmaf(wih1[0], xt, b1[0]), 0.0f);
        u64 g1 = pack2(fmaf(wih1[1], xt, b1[1]), 0.0f);
        u64 g2 = pack2(fmaf(wih1[2], xt, b1[2]), 0.0f);
        u64 g3 = pack2(fmaf(wih1[3], xt, b1[3]), 0.0f);
#pragma unroll
        for (int p = 0; p < 5; p++) {
            g0 = ffma2(whh1[0][p], w[p], g0);
            g1 = ffma2(whh1[1][p], w[p], g1);
            g2 = ffma2(whh1[2][p], w[p], g2);
            g3 = ffma2(whh1[3][p], w[p], g3);
        }
        float h1 = cell_update_h(psum(g0), psum(g1), psum(g2), psum(g3), c1);
        if (alane) sw[SW_H1 + gc * 12 + k] = h1;

        // layer 2 (vd holds h2(t-1))
        load_vec10(sw + SW_H1 + gc * 12, w);     // h1(t)
        u64 a0 = pack2(b2[0], 0.0f), a1 = pack2(b2[1], 0.0f);
        u64 a2 = pack2(b2[2], 0.0f), a3 = pack2(b2[3], 0.0f);
#pragma unroll
        for (int p = 0; p < 5; p++) {
            a0 = ffma2(wih2[0][p], w[p], a0);  a0 = ffma2(whh2[0][p], vd[p], a0);
            a1 = ffma2(wih2[1][p], w[p], a1);  a1 = ffma2(whh2[1][p], vd[p], a1);
            a2 = ffma2(wih2[2][p], w[p], a2);  a2 = ffma2(whh2[2][p], vd[p], a2);
            a3 = ffma2(wih2[3][p], w[p], a3);  a3 = ffma2(whh2[3][p], vd[p], a3);
        }
        float h2 = cell_update_h(psum(a0), psum(a1), psum(a2), psum(a3), c2);
        float* hslot = sw + SW_HIST + (t & 15) * 36 + gc * 12;
        if (alane) hslot[k] = h2;
        load_vec10(hslot, vd);                   // fresh h2(t)

        // head from fresh h2(t) (feedback value; also stored when t >= T)
        u64 Y = pack2(blin, 0.0f);
#pragma unroll
        for (int p = 0; p < 5; p++) Y = ffma2(wlinp[p], vd[p], Y);
        float y = psum(Y);
        xt = y;
        if (t >= T && alane && k == 0 && b < B)
            out[(size_t)b * outT + t] = y;

        // once h2(T-1) is in slot 15, flush the last main block T-16..T-1
        if (t == T - 1) flush_y(T - 16);
    }
}

extern "C" void kernel_launch(void* const* d_in, const int* in_sizes, int n_in,
                              void* d_out, int out_size)
{
    const float* x     = (const float*)d_in[0];
    const float* W_ih1 = (const float*)d_in[1];
    const float* W_hh1 = (const float*)d_in[2];
    const float* b_ih1 = (const float*)d_in[3];
    const float* b_hh1 = (const float*)d_in[4];
    const float* W_ih2 = (const float*)d_in[5];
    const float* W_hh2 = (const float*)d_in[6];
    const float* b_ih2 = (const float*)d_in[7];
    const float* b_hh2 = (const float*)d_in[8];
    const float* W_lin = (const float*)d_in[9];
    const float* b_lin = (const float*)d_in[10];
    float* out = (float*)d_out;

    const int T = T_FIXED;
    const int B = in_sizes[0] / T;          // 2048
    const int outT = out_size / B;          // T + future = 1088

    // 3 batches per warp, 4 warps per block -> 12 batches/block (R13 grid)
    const int nWarps  = (B + 2) / 3;                    // 683
    const int nBlocks = (nWarps + 3) / 4;               // 171
    lstm2_seq_kernel<<<nBlocks, 128>>>(
        x, W_ih1, W_hh1, b_ih1, b_hh1,
        W_ih2, W_hh2, b_ih2, b_hh2,
        W_lin, b_lin, out, B, T, outT);
}